// round 10
// baseline (speedup 1.0000x reference)
#include <cuda_runtime.h>
#include <cstdint>
#include <math.h>

// Problem constants
#define BB 4
#define NN 2048
#define EE 768
#define HH 8
#define DD 96
#define SCALING 0.1020620726159658f   // 96^-0.5

// Scratch (static device globals; no allocation). All tf32-pre-rounded.
// perm8: within-8 permutation k'=(k&3)*2+(k>>2).
__device__ float g_Q[BB * HH * NN * DD];    // [b][h][n][d'] permuted
__device__ float g_K[BB * HH * NN * DD];    // [b][h][n][d'] permuted
__device__ float g_V[BB * HH * NN * DD];    // [b][h][n][d]  plain
__device__ float g_ctx[BB * NN * EE];       // [b][n][e'] permuted e
__device__ float g_xr[BB * NN * EE];        // rounded x, permuted k
__device__ float g_Wqkvr[EE * 3 * EE];      // rounded Wqkv [768][2304] plain
__device__ float g_Wprojr[EE * EE];         // rounded Wproj [768][768] plain

// ---------------------------------------------------------------------------
// helpers
// ---------------------------------------------------------------------------
__device__ __forceinline__ uint32_t tf32r(float x) {
    uint32_t y;
    asm("cvt.rna.tf32.f32 %0, %1;" : "=r"(y) : "f"(x));
    return y;
}

__device__ __forceinline__ int perm8(int k) {           // within-8 permutation
    return (k & ~7) | (((k & 3) << 1) | ((k >> 2) & 1));
}

__device__ __forceinline__ void mma_tf32(float* c, const uint32_t* a,
                                         const uint32_t* b) {
    asm volatile(
        "mma.sync.aligned.m16n8k8.row.col.f32.tf32.tf32.f32 "
        "{%0,%1,%2,%3}, {%4,%5,%6,%7}, {%8,%9}, {%0,%1,%2,%3};\n"
        : "+f"(c[0]), "+f"(c[1]), "+f"(c[2]), "+f"(c[3])
        : "r"(a[0]), "r"(a[1]), "r"(a[2]), "r"(a[3]), "r"(b[0]), "r"(b[1]));
}

__device__ __forceinline__ void cp16(void* smem_ptr, const void* gptr) {
    uint32_t sa = (uint32_t)__cvta_generic_to_shared(smem_ptr);
    asm volatile("cp.async.cg.shared.global [%0], [%1], 16;"
                 :: "r"(sa), "l"(gptr));
}
#define CP_COMMIT() asm volatile("cp.async.commit_group;" ::: "memory")
#define CP_WAIT0()  asm volatile("cp.async.wait_group 0;" ::: "memory")

// ---------------------------------------------------------------------------
// Pre-pass A: round + k-permute x -> g_xr
// ---------------------------------------------------------------------------
__global__ void round_perm_x(const float4* __restrict__ src, int n4)
{
    int i = blockIdx.x * blockDim.x + threadIdx.x;
    if (i >= n4) return;
    float4 v = src[i];
    int base = i * 4;
    int row = base / 768, k = base % 768;
    float* dst = g_xr + (size_t)row * 768;
    dst[perm8(k + 0)] = __uint_as_float(tf32r(v.x));
    dst[perm8(k + 1)] = __uint_as_float(tf32r(v.y));
    dst[perm8(k + 2)] = __uint_as_float(tf32r(v.z));
    dst[perm8(k + 3)] = __uint_as_float(tf32r(v.w));
}

// ---------------------------------------------------------------------------
// Pre-pass B: plain tf32 rounding for weights (B-side perm happens at cp dst)
// ---------------------------------------------------------------------------
__global__ void round_into(const float4* __restrict__ src, int n4, int sel)
{
    float4* dst = sel ? (float4*)g_Wqkvr : (float4*)g_Wprojr;
    int i = blockIdx.x * blockDim.x + threadIdx.x;
    if (i < n4) {
        float4 v = src[i];
        v.x = __uint_as_float(tf32r(v.x));
        v.y = __uint_as_float(tf32r(v.y));
        v.z = __uint_as_float(tf32r(v.z));
        v.w = __uint_as_float(tf32r(v.w));
        dst[i] = v;
    }
}

// ---------------------------------------------------------------------------
// Tensor-core tf32 GEMM, k-permuted operands, cp.async double-buffered.
// C[8192,LDW] = A[8192,768] @ W[768,LDW] + bias. Tile 128x128x32.
// 8 warps, warp tile 64x32 (wm=wid&1, wn=wid>>1): 4 m-frags x 4 n-frags.
// A (gmem pre-permuted k) -> smem [128][40], frag pair = one LDS.64.
// W (plain) -> smem rows permuted AT CP TIME: dst row perm8(k), [32][132].
// Per k-step: 8 LDS.64 + 8 LDS.32 + 16 HMMA (was 24 LDS.32 + 16 HMMA).
// MODE 1 (qkv): A=g_xr; scatter to g_Q/g_K (perm d) + g_V (plain).
// MODE 0 (proj): A=g_ctx (perm e); plain fp32 out.
// ---------------------------------------------------------------------------
#define APAD 40
#define BPAD 132
#define ASZ (128 * APAD)          // 5120 floats
#define BSZ (32 * BPAD)           // 4224 floats
#define GSTG (ASZ + BSZ)          // 9344 floats
#define GSMEM (2 * GSTG * 4)      // 74752 B

template<int MODE, int LDW>
__global__ __launch_bounds__(256, 2) void gemm_tc(
    const float* __restrict__ bias,
    float* __restrict__ out)
{
    extern __shared__ float sm[];
    const float* A = (MODE == 0) ? (const float*)g_ctx : (const float*)g_xr;
    const float* W = (MODE == 0) ? (const float*)g_Wprojr : (const float*)g_Wqkvr;

    const int tid  = threadIdx.x;
    const int lane = tid & 31;
    const int wid  = tid >> 5;
    const int wm   = wid & 1;        // 2 m-tiles of 64
    const int wn   = wid >> 1;       // 4 n-tiles of 32
    const int row0 = blockIdx.y * 128;
    const int col0 = blockIdx.x * 128;
    const int g    = lane >> 2;
    const int t    = lane & 3;

    float acc[4][4][4];
    #pragma unroll
    for (int ml = 0; ml < 4; ml++)
        #pragma unroll
        for (int nl = 0; nl < 4; nl++)
            #pragma unroll
            for (int e = 0; e < 4; e++) acc[ml][nl][e] = 0.f;

    auto issue = [&](int kt, int s) {
        float* sA = sm + s * GSTG;
        float* sB = sA + ASZ;
        #pragma unroll
        for (int p = 0; p < 4; p++) {
            int i = tid + p * 256;
            int m = i >> 3, k4 = i & 7;
            cp16(sA + m * APAD + k4 * 4,
                 A + (size_t)(row0 + m) * 768 + kt * 32 + k4 * 4);
        }
        #pragma unroll
        for (int p = 0; p < 4; p++) {
            int i = tid + p * 256;
            int k = i >> 5, n4 = i & 31;
            cp16(sB + perm8(k) * BPAD + n4 * 4,
                 W + (size_t)(kt * 32 + k) * LDW + col0 + n4 * 4);
        }
        CP_COMMIT();
    };

    issue(0, 0);

    #pragma unroll 1
    for (int kt = 0; kt < 24; kt++) {
        const int s = kt & 1;
        CP_WAIT0();
        __syncthreads();
        if (kt < 23) issue(kt + 1, s ^ 1);

        const uint32_t* sA = (const uint32_t*)(sm + s * GSTG);
        const uint32_t* sB = sA + ASZ;

        #pragma unroll
        for (int ks = 0; ks < 4; ks++) {
            const int k0 = ks * 8;
            uint32_t af[4][4];
            #pragma unroll
            for (int ml = 0; ml < 4; ml++) {
                const int m_off = wm * 64 + ml * 16;
                uint2 lo = *(const uint2*)&sA[(m_off + g)     * APAD + k0 + 2 * t];
                uint2 hi = *(const uint2*)&sA[(m_off + g + 8) * APAD + k0 + 2 * t];
                af[ml][0] = lo.x; af[ml][1] = hi.x;
                af[ml][2] = lo.y; af[ml][3] = hi.y;
            }
            #pragma unroll
            for (int nl = 0; nl < 4; nl++) {
                const int n_off = wn * 32 + nl * 8;
                uint32_t bf[2];
                bf[0] = sB[(k0 + 2 * t)     * BPAD + n_off + g];
                bf[1] = sB[(k0 + 2 * t + 1) * BPAD + n_off + g];
                #pragma unroll
                for (int ml = 0; ml < 4; ml++)
                    mma_tf32(acc[ml][nl], af[ml], bf);
            }
        }
    }

    // ---- epilogue ----
    if (MODE == 0) {
        #pragma unroll
        for (int ml = 0; ml < 4; ml++) {
            #pragma unroll
            for (int rh = 0; rh < 2; rh++) {
                int m = row0 + wm * 64 + ml * 16 + g + rh * 8;
                float* op = out + (size_t)m * LDW;
                #pragma unroll
                for (int nl = 0; nl < 4; nl++) {
                    int c = col0 + wn * 32 + nl * 8 + 2 * t;
                    float2 bv = *(const float2*)(bias + c);
                    float2 o;
                    o.x = acc[ml][nl][rh * 2 + 0] + bv.x;
                    o.y = acc[ml][nl][rh * 2 + 1] + bv.y;
                    *(float2*)(op + c) = o;
                }
            }
        }
    } else {
        #pragma unroll
        for (int ml = 0; ml < 4; ml++) {
            #pragma unroll
            for (int rh = 0; rh < 2; rh++) {
                int m = row0 + wm * 64 + ml * 16 + g + rh * 8;
                int b = m >> 11, n = m & 2047;
                #pragma unroll
                for (int nl = 0; nl < 4; nl++) {
                    #pragma unroll
                    for (int e = 0; e < 2; e++) {
                        int c = col0 + wn * 32 + nl * 8 + 2 * t + e;
                        float v = acc[ml][nl][rh * 2 + e] + __ldg(bias + c);
                        int sel = c % 3;
                        int hd  = c / 3;
                        int h   = hd / 96;
                        int d   = hd - h * 96;
                        float vr = __uint_as_float(tf32r(v));
                        size_t rowo = ((size_t)(b * HH + h) * NN + n) * DD;
                        if (sel == 0)      g_Q[rowo + perm8(d)] = vr;
                        else if (sel == 1) g_K[rowo + perm8(d)] = vr;
                        else               g_V[rowo + d]        = vr;
                    }
                }
            }
        }
    }
}

// ---------------------------------------------------------------------------
// Flash attention on mma.sync tf32, BN=64 keys/tile, cp.async double-buffer.
// BM=128 (8 warps x 16 rows). g_Q/g_K permuted d -> uint2 frags; V plain.
// Epilogue writes g_ctx with PERMUTED e (consumed by k-permuted proj GEMM).
// ---------------------------------------------------------------------------
#define KVPAD 104
#define KVSZ (64 * KVPAD)
#define ASTG (2 * KVSZ)
#define ASMEM (2 * ASTG * 4)       // 106496 B

__global__ __launch_bounds__(256) void attn_mma()
{
    extern __shared__ float sm[];

    const int tid  = threadIdx.x;
    const int lane = tid & 31;
    const int wid  = tid >> 5;
    const int g    = lane >> 2;
    const int t    = lane & 3;
    const int q0   = blockIdx.x * 128;
    const int bh   = blockIdx.y;
    const int b    = bh >> 3;
    const int h    = bh & 7;

    const float* Qg = g_Q + (size_t)bh * NN * DD;
    const float* Kg = g_K + (size_t)bh * NN * DD;
    const float* Vg = g_V + (size_t)bh * NN * DD;

    const int r0 = 16 * wid + g;
    const int r1 = r0 + 8;

    auto issueKV = [&](int kt, int s) {
        const int j0 = kt * 64;
        float* bK = sm + s * ASTG;
        float* bV = bK + KVSZ;
        #pragma unroll
        for (int p = 0; p < 6; p++) {
            int i  = tid + p * 256;
            int r  = i / 24, c4 = i % 24;
            cp16(bK + r * KVPAD + c4 * 4, Kg + (size_t)(j0 + r) * DD + c4 * 4);
            cp16(bV + r * KVPAD + c4 * 4, Vg + (size_t)(j0 + r) * DD + c4 * 4);
        }
        CP_COMMIT();
    };

    issueKV(0, 0);

    uint32_t qf[12][4];
    {
        const uint32_t* Q0 = (const uint32_t*)(Qg + (size_t)(q0 + r0) * DD);
        const uint32_t* Q1 = (const uint32_t*)(Qg + (size_t)(q0 + r1) * DD);
        #pragma unroll
        for (int c = 0; c < 12; c++) {
            uint2 v0 = *(const uint2*)&Q0[8 * c + 2 * t];
            uint2 v1 = *(const uint2*)&Q1[8 * c + 2 * t];
            qf[c][0] = v0.x; qf[c][2] = v0.y;
            qf[c][1] = v1.x; qf[c][3] = v1.y;
        }
    }

    float m0 = -1e30f, m1 = -1e30f, l0 = 0.f, l1 = 0.f;
    float oacc[12][4];
    #pragma unroll
    for (int dc = 0; dc < 12; dc++)
        #pragma unroll
        for (int e = 0; e < 4; e++) oacc[dc][e] = 0.f;

    #pragma unroll 1
    for (int kt = 0; kt < 32; kt++) {
        const int s = kt & 1;
        CP_WAIT0();
        __syncthreads();
        if (kt < 31) issueKV(kt + 1, s ^ 1);

        const uint32_t* sKu = (const uint32_t*)(sm + s * ASTG);
        const uint32_t* sVu = sKu + KVSZ;

        float sacc[8][4];
        #pragma unroll
        for (int nc = 0; nc < 8; nc++)
            #pragma unroll
            for (int e = 0; e < 4; e++) sacc[nc][e] = 0.f;

        #pragma unroll
        for (int kc = 0; kc < 12; kc++) {
            #pragma unroll
            for (int nc = 0; nc < 8; nc++) {
                uint2 v = *(const uint2*)&sKu[(nc * 8 + g) * KVPAD + kc * 8 + 2 * t];
                uint32_t bf[2] = { v.x, v.y };
                mma_tf32(sacc[nc], qf[kc], bf);
            }
        }

        float lm0 = sacc[0][0], lm1 = sacc[0][2];
        #pragma unroll
        for (int nc = 0; nc < 8; nc++) {
            lm0 = fmaxf(lm0, fmaxf(sacc[nc][0], sacc[nc][1]));
            lm1 = fmaxf(lm1, fmaxf(sacc[nc][2], sacc[nc][3]));
        }
        lm0 = fmaxf(lm0, __shfl_xor_sync(0xffffffffu, lm0, 1));
        lm0 = fmaxf(lm0, __shfl_xor_sync(0xffffffffu, lm0, 2));
        lm1 = fmaxf(lm1, __shfl_xor_sync(0xffffffffu, lm1, 1));
        lm1 = fmaxf(lm1, __shfl_xor_sync(0xffffffffu, lm1, 2));

        const float mn0 = fmaxf(m0, lm0);
        const float mn1 = fmaxf(m1, lm1);
        const float sc0 = __expf(m0 - mn0);
        const float sc1 = __expf(m1 - mn1);
        m0 = mn0; m1 = mn1;

        float rs0 = 0.f, rs1 = 0.f;
        #pragma unroll
        for (int nc = 0; nc < 8; nc++) {
            sacc[nc][0] = __expf(sacc[nc][0] - mn0);
            sacc[nc][1] = __expf(sacc[nc][1] - mn0);
            sacc[nc][2] = __expf(sacc[nc][2] - mn1);
            sacc[nc][3] = __expf(sacc[nc][3] - mn1);
            rs0 += sacc[nc][0] + sacc[nc][1];
            rs1 += sacc[nc][2] + sacc[nc][3];
        }
        rs0 += __shfl_xor_sync(0xffffffffu, rs0, 1);
        rs0 += __shfl_xor_sync(0xffffffffu, rs0, 2);
        rs1 += __shfl_xor_sync(0xffffffffu, rs1, 1);
        rs1 += __shfl_xor_sync(0xffffffffu, rs1, 2);
        l0 = l0 * sc0 + rs0;
        l1 = l1 * sc1 + rs1;

        if (__any_sync(0xffffffffu, (sc0 != 1.f) || (sc1 != 1.f))) {
            #pragma unroll
            for (int dc = 0; dc < 12; dc++) {
                oacc[dc][0] *= sc0; oacc[dc][1] *= sc0;
                oacc[dc][2] *= sc1; oacc[dc][3] *= sc1;
            }
        }

        const int s0 = t >> 1;
        const int s1 = s0 + 2;
        #pragma unroll
        for (int kc = 0; kc < 8; kc++) {
            uint32_t p0 = tf32r(sacc[kc][0]);
            uint32_t p1 = tf32r(sacc[kc][1]);
            uint32_t p2 = tf32r(sacc[kc][2]);
            uint32_t p3 = tf32r(sacc[kc][3]);
            uint32_t af[4];
            {
                uint32_t x0 = __shfl_sync(0xffffffffu, p0, s0, 4);
                uint32_t x1 = __shfl_sync(0xffffffffu, p1, s0, 4);
                uint32_t y0 = __shfl_sync(0xffffffffu, p0, s1, 4);
                uint32_t y1 = __shfl_sync(0xffffffffu, p1, s1, 4);
                af[0] = (t & 1) ? x1 : x0;
                af[2] = (t & 1) ? y1 : y0;
                uint32_t z0 = __shfl_sync(0xffffffffu, p2, s0, 4);
                uint32_t z1 = __shfl_sync(0xffffffffu, p3, s0, 4);
                uint32_t w0 = __shfl_sync(0xffffffffu, p2, s1, 4);
                uint32_t w1 = __shfl_sync(0xffffffffu, p3, s1, 4);
                af[1] = (t & 1) ? z1 : z0;
                af[3] = (t & 1) ? w1 : w0;
            }
            #pragma unroll
            for (int dc = 0; dc < 12; dc++) {
                uint32_t bf[2];
                bf[0] = sVu[(kc * 8 + t)     * KVPAD + dc * 8 + g];
                bf[1] = sVu[(kc * 8 + t + 4) * KVPAD + dc * 8 + g];
                mma_tf32(oacc[dc], af, bf);
            }
        }
    }

    // ---- epilogue: ctx (PERMUTED e) = tf32r((O / l) * SCALING) ----
    const float inv0 = SCALING / l0;
    const float inv1 = SCALING / l1;
    float* dst0 = g_ctx + ((size_t)b * NN + (q0 + r0)) * EE + h * DD;
    float* dst1 = g_ctx + ((size_t)b * NN + (q0 + r1)) * EE + h * DD;
    const int pa = perm8(2 * t);          // local permuted positions
    const int pb = perm8(2 * t + 1);
    #pragma unroll
    for (int dc = 0; dc < 12; dc++) {
        dst0[dc * 8 + pa] = __uint_as_float(tf32r(oacc[dc][0] * inv0));
        dst0[dc * 8 + pb] = __uint_as_float(tf32r(oacc[dc][1] * inv0));
        dst1[dc * 8 + pa] = __uint_as_float(tf32r(oacc[dc][2] * inv1));
        dst1[dc * 8 + pb] = __uint_as_float(tf32r(oacc[dc][3] * inv1));
    }
}

// ---------------------------------------------------------------------------
extern "C" void kernel_launch(void* const* d_in, const int* in_sizes, int n_in,
                              void* d_out, int out_size)
{
    const float* x     = (const float*)d_in[0];
    const float* Wqkv  = (const float*)d_in[1];
    const float* bqkv  = (const float*)d_in[2];
    const float* Wproj = (const float*)d_in[3];
    const float* bproj = (const float*)d_in[4];
    float* out = (float*)d_out;

    cudaFuncSetAttribute(gemm_tc<1, 2304>,
                         cudaFuncAttributeMaxDynamicSharedMemorySize, GSMEM);
    cudaFuncSetAttribute(gemm_tc<0, 768>,
                         cudaFuncAttributeMaxDynamicSharedMemorySize, GSMEM);
    cudaFuncSetAttribute(attn_mma,
                         cudaFuncAttributeMaxDynamicSharedMemorySize, ASMEM);

    round_perm_x<<<(1572864 + 255) / 256, 256>>>((const float4*)x, 1572864);
    round_into<<<(442368  + 255) / 256, 256>>>((const float4*)Wqkv,  442368, 1);
    round_into<<<(147456  + 255) / 256, 256>>>((const float4*)Wproj, 147456, 0);

    dim3 g1(2304 / 128, 8192 / 128);      // 18 x 64
    gemm_tc<1, 2304><<<g1, 256, GSMEM>>>(bqkv, nullptr);

    dim3 g2(NN / 128, BB * HH);           // 16 x 32
    attn_mma<<<g2, 256, ASMEM>>>();

    dim3 g3(768 / 128, 8192 / 128);       // 6 x 64
    gemm_tc<0, 768><<<g3, 256, GSMEM>>>(bproj, out);
}

// round 11
// speedup vs baseline: 1.0850x; 1.0850x over previous
#include <cuda_runtime.h>
#include <cstdint>
#include <math.h>

// Problem constants
#define BB 4
#define NN 2048
#define EE 768
#define HH 8
#define DD 96
#define SCALING 0.1020620726159658f   // 96^-0.5

// Scratch (static device globals; no allocation). All tf32-pre-rounded.
// g_Q/g_K: within-8 d permutation d'=(d&3)*2+(d>>2)  (uint2 frag loads).
// g_V: KEY-ROW permutation n'=(n&~7)|((n&1)*4+((n>>1)&3)) (shuffle-free PV).
__device__ float g_Q[BB * HH * NN * DD];    // [b][h][n][d'] perm d
__device__ float g_K[BB * HH * NN * DD];    // [b][h][n][d'] perm d
__device__ float g_V[BB * HH * NN * DD];    // [b][h][n'][d] perm rows
__device__ float g_ctx[BB * NN * EE];       // [b][n][e] plain
__device__ float g_xr[BB * NN * EE];        // rounded x (plain)
__device__ float g_Wqkvr[EE * 3 * EE];      // rounded Wqkv (plain)
__device__ float g_Wprojr[EE * EE];         // rounded Wproj (plain)

// ---------------------------------------------------------------------------
// helpers
// ---------------------------------------------------------------------------
__device__ __forceinline__ uint32_t tf32r(float x) {
    uint32_t y;
    asm("cvt.rna.tf32.f32 %0, %1;" : "=r"(y) : "f"(x));
    return y;
}

__device__ __forceinline__ int perm8(int k) {        // pos p holds col perm8^-1? see use
    return (k & ~7) | (((k & 3) << 1) | ((k >> 2) & 1));
}
__device__ __forceinline__ int invperm8(int k) {     // inverse of perm8 within 8
    return ((k & 1) << 2) | ((k >> 1) & 3);
}

__device__ __forceinline__ void mma_tf32(float* c, const uint32_t* a,
                                         const uint32_t* b) {
    asm volatile(
        "mma.sync.aligned.m16n8k8.row.col.f32.tf32.tf32.f32 "
        "{%0,%1,%2,%3}, {%4,%5,%6,%7}, {%8,%9}, {%0,%1,%2,%3};\n"
        : "+f"(c[0]), "+f"(c[1]), "+f"(c[2]), "+f"(c[3])
        : "r"(a[0]), "r"(a[1]), "r"(a[2]), "r"(a[3]), "r"(b[0]), "r"(b[1]));
}

__device__ __forceinline__ void cp16(void* smem_ptr, const void* gptr) {
    uint32_t sa = (uint32_t)__cvta_generic_to_shared(smem_ptr);
    asm volatile("cp.async.cg.shared.global [%0], [%1], 16;"
                 :: "r"(sa), "l"(gptr));
}
#define CP_COMMIT() asm volatile("cp.async.commit_group;" ::: "memory")
#define CP_WAIT0()  asm volatile("cp.async.wait_group 0;" ::: "memory")

// ---------------------------------------------------------------------------
// Kernel 0: tf32-round inputs into device scratch (dst resolved device-side)
// ---------------------------------------------------------------------------
__global__ void round_into(const float4* __restrict__ src, int n4, int sel)
{
    float4* dst = (sel == 0) ? (float4*)g_xr
               : (sel == 1) ? (float4*)g_Wqkvr
                            : (float4*)g_Wprojr;
    int i = blockIdx.x * blockDim.x + threadIdx.x;
    if (i < n4) {
        float4 v = src[i];
        v.x = __uint_as_float(tf32r(v.x));
        v.y = __uint_as_float(tf32r(v.y));
        v.z = __uint_as_float(tf32r(v.z));
        v.w = __uint_as_float(tf32r(v.w));
        dst[i] = v;
    }
}

// ---------------------------------------------------------------------------
// Tensor-core tf32 GEMM (validated R7/R9 shape): cp.async double-buffer.
// C[8192,LDW] = A[8192,768] @ W[768,LDW] + bias. Tile 128x128x32, 8 warps,
// warp tile 32x64, scalar fragment LDS (measured fastest variant).
// MODE 1 (qkv): scatter to g_Q/g_K (perm d), g_V (perm row n).
// MODE 0 (proj): A=g_ctx, write fp32 out.
// ---------------------------------------------------------------------------
#define APAD 36
#define BPAD 136
#define ASZ (128 * APAD)
#define BSZ (32 * BPAD)
#define GSTG (ASZ + BSZ)
#define GSMEM (2 * GSTG * 4)

template<int MODE, int LDW>
__global__ __launch_bounds__(256, 2) void gemm_tc(
    const float* __restrict__ bias,
    float* __restrict__ out)
{
    extern __shared__ float sm[];
    const float* A = (MODE == 0) ? (const float*)g_ctx : (const float*)g_xr;
    const float* W = (MODE == 0) ? (const float*)g_Wprojr : (const float*)g_Wqkvr;

    const int tid  = threadIdx.x;
    const int lane = tid & 31;
    const int wid  = tid >> 5;
    const int wm   = wid & 3;
    const int wn   = wid >> 2;
    const int row0 = blockIdx.y * 128;
    const int col0 = blockIdx.x * 128;
    const int g    = lane >> 2;
    const int t    = lane & 3;

    float acc[2][8][4];
    #pragma unroll
    for (int ml = 0; ml < 2; ml++)
        #pragma unroll
        for (int nl = 0; nl < 8; nl++)
            #pragma unroll
            for (int e = 0; e < 4; e++) acc[ml][nl][e] = 0.f;

    auto issue = [&](int kt, int s) {
        float* sA = sm + s * GSTG;
        float* sB = sA + ASZ;
        #pragma unroll
        for (int p = 0; p < 4; p++) {
            int i = tid + p * 256;
            int m = i >> 3, k4 = i & 7;
            cp16(sA + m * APAD + k4 * 4,
                 A + (size_t)(row0 + m) * 768 + kt * 32 + k4 * 4);
        }
        #pragma unroll
        for (int p = 0; p < 4; p++) {
            int i = tid + p * 256;
            int k = i >> 5, n4 = i & 31;
            cp16(sB + k * BPAD + n4 * 4,
                 W + (size_t)(kt * 32 + k) * LDW + col0 + n4 * 4);
        }
        CP_COMMIT();
    };

    issue(0, 0);

    #pragma unroll 1
    for (int kt = 0; kt < 24; kt++) {
        const int s = kt & 1;
        CP_WAIT0();
        __syncthreads();
        if (kt < 23) issue(kt + 1, s ^ 1);

        const uint32_t* sA = (const uint32_t*)(sm + s * GSTG);
        const uint32_t* sB = sA + ASZ;

        #pragma unroll
        for (int ks = 0; ks < 4; ks++) {
            const int k0 = ks * 8;
            uint32_t af[2][4];
            #pragma unroll
            for (int ml = 0; ml < 2; ml++) {
                const int m_off = wm * 32 + ml * 16;
                af[ml][0] = sA[(m_off + g)     * APAD + k0 + t];
                af[ml][1] = sA[(m_off + g + 8) * APAD + k0 + t];
                af[ml][2] = sA[(m_off + g)     * APAD + k0 + t + 4];
                af[ml][3] = sA[(m_off + g + 8) * APAD + k0 + t + 4];
            }
            #pragma unroll
            for (int nl = 0; nl < 8; nl++) {
                const int n_off = wn * 64 + nl * 8;
                uint32_t bf[2];
                bf[0] = sB[(k0 + t)     * BPAD + n_off + g];
                bf[1] = sB[(k0 + t + 4) * BPAD + n_off + g];
                mma_tf32(acc[0][nl], af[0], bf);
                mma_tf32(acc[1][nl], af[1], bf);
            }
        }
    }

    // ---- epilogue ----
    if (MODE == 0) {
        #pragma unroll
        for (int ml = 0; ml < 2; ml++) {
            #pragma unroll
            for (int rh = 0; rh < 2; rh++) {
                int m = row0 + wm * 32 + ml * 16 + g + rh * 8;
                float* op = out + (size_t)m * LDW;
                #pragma unroll
                for (int nl = 0; nl < 8; nl++) {
                    int c = col0 + wn * 64 + nl * 8 + 2 * t;
                    float2 bv = *(const float2*)(bias + c);
                    float2 o;
                    o.x = acc[ml][nl][rh * 2 + 0] + bv.x;
                    o.y = acc[ml][nl][rh * 2 + 1] + bv.y;
                    *(float2*)(op + c) = o;
                }
            }
        }
    } else {
        #pragma unroll
        for (int ml = 0; ml < 2; ml++) {
            #pragma unroll
            for (int rh = 0; rh < 2; rh++) {
                int m = row0 + wm * 32 + ml * 16 + g + rh * 8;
                int b = m >> 11, n = m & 2047;
                int np = (n & ~7) | invperm8(n & 7);   // V row permutation
                #pragma unroll
                for (int nl = 0; nl < 8; nl++) {
                    #pragma unroll
                    for (int e = 0; e < 2; e++) {
                        int c = col0 + wn * 64 + nl * 8 + 2 * t + e;
                        float v = acc[ml][nl][rh * 2 + e] + __ldg(bias + c);
                        int sel = c % 3;
                        int hd  = c / 3;
                        int h   = hd / 96;
                        int d   = hd - h * 96;
                        float vr = __uint_as_float(tf32r(v));
                        size_t base = (size_t)(b * HH + h) * NN;
                        if (sel == 0)      g_Q[(base + n) * DD + perm8(d)] = vr;
                        else if (sel == 1) g_K[(base + n) * DD + perm8(d)] = vr;
                        else               g_V[(base + np) * DD + d]       = vr;
                    }
                }
            }
        }
    }
}

// ---------------------------------------------------------------------------
// Flash attention on mma.sync tf32, BN=64 keys/tile, cp.async double-buffer.
// BM=128 (8 warps x 16 rows -> warp-local softmax).
// g_Q/g_K permuted d -> uint2 frags. g_V rows pre-permuted in gmem so the
// S C-fragment registers feed the PV MMA A-operand DIRECTLY (no shuffles):
//   A pos j holds P col perm8(j); V smem row j holds V key perm8(j).
// ---------------------------------------------------------------------------
#define KVPAD 104
#define KVSZ (64 * KVPAD)
#define ASTG (2 * KVSZ)
#define ASMEM (2 * ASTG * 4)       // 106496 B

__global__ __launch_bounds__(256) void attn_mma()
{
    extern __shared__ float sm[];

    const int tid  = threadIdx.x;
    const int lane = tid & 31;
    const int wid  = tid >> 5;
    const int g    = lane >> 2;
    const int t    = lane & 3;
    const int q0   = blockIdx.x * 128;
    const int bh   = blockIdx.y;
    const int b    = bh >> 3;
    const int h    = bh & 7;

    const float* Qg = g_Q + (size_t)bh * NN * DD;
    const float* Kg = g_K + (size_t)bh * NN * DD;
    const float* Vg = g_V + (size_t)bh * NN * DD;

    const int r0 = 16 * wid + g;
    const int r1 = r0 + 8;

    auto issueKV = [&](int kt, int s) {
        const int j0 = kt * 64;
        float* bK = sm + s * ASTG;
        float* bV = bK + KVSZ;
        #pragma unroll
        for (int p = 0; p < 6; p++) {
            int i  = tid + p * 256;
            int r  = i / 24, c4 = i % 24;
            cp16(bK + r * KVPAD + c4 * 4, Kg + (size_t)(j0 + r) * DD + c4 * 4);
            cp16(bV + r * KVPAD + c4 * 4, Vg + (size_t)(j0 + r) * DD + c4 * 4);
        }
        CP_COMMIT();
    };

    issueKV(0, 0);

    uint32_t qf[12][4];
    {
        const uint32_t* Q0 = (const uint32_t*)(Qg + (size_t)(q0 + r0) * DD);
        const uint32_t* Q1 = (const uint32_t*)(Qg + (size_t)(q0 + r1) * DD);
        #pragma unroll
        for (int c = 0; c < 12; c++) {
            uint2 v0 = *(const uint2*)&Q0[8 * c + 2 * t];
            uint2 v1 = *(const uint2*)&Q1[8 * c + 2 * t];
            qf[c][0] = v0.x; qf[c][2] = v0.y;
            qf[c][1] = v1.x; qf[c][3] = v1.y;
        }
    }

    float m0 = -1e30f, m1 = -1e30f, l0 = 0.f, l1 = 0.f;
    float oacc[12][4];
    #pragma unroll
    for (int dc = 0; dc < 12; dc++)
        #pragma unroll
        for (int e = 0; e < 4; e++) oacc[dc][e] = 0.f;

    #pragma unroll 1
    for (int kt = 0; kt < 32; kt++) {
        const int s = kt & 1;
        CP_WAIT0();
        __syncthreads();
        if (kt < 31) issueKV(kt + 1, s ^ 1);

        const uint32_t* sKu = (const uint32_t*)(sm + s * ASTG);
        const uint32_t* sVu = sKu + KVSZ;

        // ---- S = Q K^T : 8 n-chunks x 12 k-chunks ----
        float sacc[8][4];
        #pragma unroll
        for (int nc = 0; nc < 8; nc++)
            #pragma unroll
            for (int e = 0; e < 4; e++) sacc[nc][e] = 0.f;

        #pragma unroll
        for (int kc = 0; kc < 12; kc++) {
            #pragma unroll
            for (int nc = 0; nc < 8; nc++) {
                uint2 v = *(const uint2*)&sKu[(nc * 8 + g) * KVPAD + kc * 8 + 2 * t];
                uint32_t bf[2] = { v.x, v.y };
                mma_tf32(sacc[nc], qf[kc], bf);
            }
        }

        // ---- online softmax (warp-local rows r0, r1) ----
        float lm0 = sacc[0][0], lm1 = sacc[0][2];
        #pragma unroll
        for (int nc = 0; nc < 8; nc++) {
            lm0 = fmaxf(lm0, fmaxf(sacc[nc][0], sacc[nc][1]));
            lm1 = fmaxf(lm1, fmaxf(sacc[nc][2], sacc[nc][3]));
        }
        lm0 = fmaxf(lm0, __shfl_xor_sync(0xffffffffu, lm0, 1));
        lm0 = fmaxf(lm0, __shfl_xor_sync(0xffffffffu, lm0, 2));
        lm1 = fmaxf(lm1, __shfl_xor_sync(0xffffffffu, lm1, 1));
        lm1 = fmaxf(lm1, __shfl_xor_sync(0xffffffffu, lm1, 2));

        const float mn0 = fmaxf(m0, lm0);
        const float mn1 = fmaxf(m1, lm1);
        const float sc0 = __expf(m0 - mn0);
        const float sc1 = __expf(m1 - mn1);
        m0 = mn0; m1 = mn1;

        float rs0 = 0.f, rs1 = 0.f;
        #pragma unroll
        for (int nc = 0; nc < 8; nc++) {
            sacc[nc][0] = __expf(sacc[nc][0] - mn0);
            sacc[nc][1] = __expf(sacc[nc][1] - mn0);
            sacc[nc][2] = __expf(sacc[nc][2] - mn1);
            sacc[nc][3] = __expf(sacc[nc][3] - mn1);
            rs0 += sacc[nc][0] + sacc[nc][1];
            rs1 += sacc[nc][2] + sacc[nc][3];
        }
        rs0 += __shfl_xor_sync(0xffffffffu, rs0, 1);
        rs0 += __shfl_xor_sync(0xffffffffu, rs0, 2);
        rs1 += __shfl_xor_sync(0xffffffffu, rs1, 1);
        rs1 += __shfl_xor_sync(0xffffffffu, rs1, 2);
        l0 = l0 * sc0 + rs0;
        l1 = l1 * sc1 + rs1;

        if (__any_sync(0xffffffffu, (sc0 != 1.f) || (sc1 != 1.f))) {
            #pragma unroll
            for (int dc = 0; dc < 12; dc++) {
                oacc[dc][0] *= sc0; oacc[dc][1] *= sc0;
                oacc[dc][2] *= sc1; oacc[dc][3] *= sc1;
            }
        }

        // ---- O += P @ V : C-frags feed A directly (V rows pre-permuted) ----
        #pragma unroll
        for (int kc = 0; kc < 8; kc++) {
            uint32_t af[4];
            af[0] = tf32r(sacc[kc][0]);   // (row g,   pos t   -> col 2t)
            af[1] = tf32r(sacc[kc][2]);   // (row g+8, pos t)
            af[2] = tf32r(sacc[kc][1]);   // (row g,   pos t+4 -> col 2t+1)
            af[3] = tf32r(sacc[kc][3]);   // (row g+8, pos t+4)
            #pragma unroll
            for (int dc = 0; dc < 12; dc++) {
                uint32_t bf[2];
                bf[0] = sVu[(kc * 8 + t)     * KVPAD + dc * 8 + g];
                bf[1] = sVu[(kc * 8 + t + 4) * KVPAD + dc * 8 + g];
                mma_tf32(oacc[dc], af, bf);
            }
        }
    }

    // ---- epilogue: ctx = tf32r((O / l) * SCALING), plain e layout ----
    const float inv0 = SCALING / l0;
    const float inv1 = SCALING / l1;
    float* dst0 = g_ctx + ((size_t)b * NN + (q0 + r0)) * EE + h * DD;
    float* dst1 = g_ctx + ((size_t)b * NN + (q0 + r1)) * EE + h * DD;
    #pragma unroll
    for (int dc = 0; dc < 12; dc++) {
        float2 o0, o1;
        o0.x = __uint_as_float(tf32r(oacc[dc][0] * inv0));
        o0.y = __uint_as_float(tf32r(oacc[dc][1] * inv0));
        o1.x = __uint_as_float(tf32r(oacc[dc][2] * inv1));
        o1.y = __uint_as_float(tf32r(oacc[dc][3] * inv1));
        *(float2*)(dst0 + dc * 8 + 2 * t) = o0;
        *(float2*)(dst1 + dc * 8 + 2 * t) = o1;
    }
}

// ---------------------------------------------------------------------------
extern "C" void kernel_launch(void* const* d_in, const int* in_sizes, int n_in,
                              void* d_out, int out_size)
{
    const float* x     = (const float*)d_in[0];
    const float* Wqkv  = (const float*)d_in[1];
    const float* bqkv  = (const float*)d_in[2];
    const float* Wproj = (const float*)d_in[3];
    const float* bproj = (const float*)d_in[4];
    float* out = (float*)d_out;

    cudaFuncSetAttribute(gemm_tc<1, 2304>,
                         cudaFuncAttributeMaxDynamicSharedMemorySize, GSMEM);
    cudaFuncSetAttribute(gemm_tc<0, 768>,
                         cudaFuncAttributeMaxDynamicSharedMemorySize, GSMEM);
    cudaFuncSetAttribute(attn_mma,
                         cudaFuncAttributeMaxDynamicSharedMemorySize, ASMEM);

    round_into<<<(1572864 + 255) / 256, 256>>>((const float4*)x,     1572864, 0);
    round_into<<<(442368  + 255) / 256, 256>>>((const float4*)Wqkv,  442368,  1);
    round_into<<<(147456  + 255) / 256, 256>>>((const float4*)Wproj, 147456,  2);

    dim3 g1(2304 / 128, 8192 / 128);      // 18 x 64
    gemm_tc<1, 2304><<<g1, 256, GSMEM>>>(bqkv, nullptr);

    dim3 g2(NN / 128, BB * HH);           // 16 x 32
    attn_mma<<<g2, 256, ASMEM>>>();

    dim3 g3(768 / 128, 8192 / 128);       // 6 x 64
    gemm_tc<0, 768><<<g3, 256, GSMEM>>>(bproj, out);
}

// round 13
// speedup vs baseline: 1.1223x; 1.0344x over previous
#include <cuda_runtime.h>
#include <cstdint>
#include <math.h>

// Problem constants
#define BB 4
#define NN 2048
#define EE 768
#define HH 8
#define DD 96
#define SCALING 0.1020620726159658f   // 96^-0.5

// Scratch (static device globals; no allocation). All tf32-pre-rounded.
// g_Q/g_K: within-8 d permutation d'=(d&3)*2+(d>>2)  (uint2 frag loads).
// g_V: KEY-ROW permutation n'=(n&~7)|invperm8(n&7) (shuffle-free PV).
__device__ float g_Q[BB * HH * NN * DD];    // [b][h][n][d'] perm d
__device__ float g_K[BB * HH * NN * DD];    // [b][h][n][d'] perm d
__device__ float g_V[BB * HH * NN * DD];    // [b][h][n'][d] perm rows
__device__ float g_ctx[BB * NN * EE];       // [b][n][e] plain
__device__ float g_xr[BB * NN * EE];        // rounded x (plain)
__device__ float g_Wqkvr[EE * 3 * EE];      // rounded Wqkv (plain)
__device__ float g_Wprojr[EE * EE];         // rounded Wproj (plain)

// ---------------------------------------------------------------------------
// helpers
// ---------------------------------------------------------------------------
__device__ __forceinline__ uint32_t tf32r(float x) {
    uint32_t y;
    asm("cvt.rna.tf32.f32 %0, %1;" : "=r"(y) : "f"(x));
    return y;
}

__device__ __forceinline__ int perm8(int k) {
    return (k & ~7) | (((k & 3) << 1) | ((k >> 2) & 1));
}
__device__ __forceinline__ int invperm8(int k) {
    return ((k & 1) << 2) | ((k >> 1) & 3);
}

__device__ __forceinline__ void mma_tf32(float* c, const uint32_t* a,
                                         const uint32_t* b) {
    asm volatile(
        "mma.sync.aligned.m16n8k8.row.col.f32.tf32.tf32.f32 "
        "{%0,%1,%2,%3}, {%4,%5,%6,%7}, {%8,%9}, {%0,%1,%2,%3};\n"
        : "+f"(c[0]), "+f"(c[1]), "+f"(c[2]), "+f"(c[3])
        : "r"(a[0]), "r"(a[1]), "r"(a[2]), "r"(a[3]), "r"(b[0]), "r"(b[1]));
}

__device__ __forceinline__ void cp16(void* smem_ptr, const void* gptr) {
    uint32_t sa = (uint32_t)__cvta_generic_to_shared(smem_ptr);
    asm volatile("cp.async.cg.shared.global [%0], [%1], 16;"
                 :: "r"(sa), "l"(gptr));
}
#define CP_COMMIT() asm volatile("cp.async.commit_group;" ::: "memory")
#define CP_WAIT0()  asm volatile("cp.async.wait_group 0;" ::: "memory")

// ---------------------------------------------------------------------------
// Kernel 0: tf32-round ALL inputs in ONE launch (partitioned index space).
// ALL COUNTS IN FLOAT4 UNITS:
//   x:     4*2048*768 = 6291456 floats = 1572864 float4
//   Wqkv:  768*2304   = 1769472 floats =  442368 float4
//   Wproj: 768*768    =  589824 floats =  147456 float4
// ---------------------------------------------------------------------------
#define NX4 1572864
#define NW4 110592      // unused (kept for clarity below) -- see real defs
#undef  NW4
#define NW4 442368
#define NP4 147456

__global__ void round_all(const float4* __restrict__ sx,
                          const float4* __restrict__ sw,
                          const float4* __restrict__ sp)
{
    int i = blockIdx.x * blockDim.x + threadIdx.x;
    const float4* src;
    float4* dst;
    int j = i;
    if (j < NX4)              { src = sx; dst = (float4*)g_xr; }
    else if (j < NX4 + NW4)   { j -= NX4; src = sw; dst = (float4*)g_Wqkvr; }
    else if (j < NX4 + NW4 + NP4) { j -= NX4 + NW4; src = sp; dst = (float4*)g_Wprojr; }
    else return;
    float4 v = src[j];
    v.x = __uint_as_float(tf32r(v.x));
    v.y = __uint_as_float(tf32r(v.y));
    v.z = __uint_as_float(tf32r(v.z));
    v.w = __uint_as_float(tf32r(v.w));
    dst[j] = v;
}

// ---------------------------------------------------------------------------
// Tensor-core tf32 GEMM (validated R7/R9 shape, frozen): cp.async 2-stage.
// C[8192,LDW] = A[8192,768] @ W[768,LDW] + bias. Tile 128x128x32, 8 warps,
// warp tile 32x64, scalar fragment LDS.
// MODE 1 (qkv): scatter to g_Q/g_K (perm d), g_V (perm row n).
// MODE 0 (proj): A=g_ctx, write fp32 out.
// ---------------------------------------------------------------------------
#define APAD 36
#define BPAD 136
#define ASZ (128 * APAD)
#define BSZ (32 * BPAD)
#define GSTG (ASZ + BSZ)
#define GSMEM (2 * GSTG * 4)

template<int MODE, int LDW>
__global__ __launch_bounds__(256, 2) void gemm_tc(
    const float* __restrict__ bias,
    float* __restrict__ out)
{
    extern __shared__ float sm[];
    const float* A = (MODE == 0) ? (const float*)g_ctx : (const float*)g_xr;
    const float* W = (MODE == 0) ? (const float*)g_Wprojr : (const float*)g_Wqkvr;

    const int tid  = threadIdx.x;
    const int lane = tid & 31;
    const int wid  = tid >> 5;
    const int wm   = wid & 3;
    const int wn   = wid >> 2;
    const int row0 = blockIdx.y * 128;
    const int col0 = blockIdx.x * 128;
    const int g    = lane >> 2;
    const int t    = lane & 3;

    float acc[2][8][4];
    #pragma unroll
    for (int ml = 0; ml < 2; ml++)
        #pragma unroll
        for (int nl = 0; nl < 8; nl++)
            #pragma unroll
            for (int e = 0; e < 4; e++) acc[ml][nl][e] = 0.f;

    auto issue = [&](int kt, int s) {
        float* sA = sm + s * GSTG;
        float* sB = sA + ASZ;
        #pragma unroll
        for (int p = 0; p < 4; p++) {
            int i = tid + p * 256;
            int m = i >> 3, k4 = i & 7;
            cp16(sA + m * APAD + k4 * 4,
                 A + (size_t)(row0 + m) * 768 + kt * 32 + k4 * 4);
        }
        #pragma unroll
        for (int p = 0; p < 4; p++) {
            int i = tid + p * 256;
            int k = i >> 5, n4 = i & 31;
            cp16(sB + k * BPAD + n4 * 4,
                 W + (size_t)(kt * 32 + k) * LDW + col0 + n4 * 4);
        }
        CP_COMMIT();
    };

    issue(0, 0);

    #pragma unroll 1
    for (int kt = 0; kt < 24; kt++) {
        const int s = kt & 1;
        CP_WAIT0();
        __syncthreads();
        if (kt < 23) issue(kt + 1, s ^ 1);

        const uint32_t* sA = (const uint32_t*)(sm + s * GSTG);
        const uint32_t* sB = sA + ASZ;

        #pragma unroll
        for (int ks = 0; ks < 4; ks++) {
            const int k0 = ks * 8;
            uint32_t af[2][4];
            #pragma unroll
            for (int ml = 0; ml < 2; ml++) {
                const int m_off = wm * 32 + ml * 16;
                af[ml][0] = sA[(m_off + g)     * APAD + k0 + t];
                af[ml][1] = sA[(m_off + g + 8) * APAD + k0 + t];
                af[ml][2] = sA[(m_off + g)     * APAD + k0 + t + 4];
                af[ml][3] = sA[(m_off + g + 8) * APAD + k0 + t + 4];
            }
            #pragma unroll
            for (int nl = 0; nl < 8; nl++) {
                const int n_off = wn * 64 + nl * 8;
                uint32_t bf[2];
                bf[0] = sB[(k0 + t)     * BPAD + n_off + g];
                bf[1] = sB[(k0 + t + 4) * BPAD + n_off + g];
                mma_tf32(acc[0][nl], af[0], bf);
                mma_tf32(acc[1][nl], af[1], bf);
            }
        }
    }

    // ---- epilogue ----
    if (MODE == 0) {
        #pragma unroll
        for (int ml = 0; ml < 2; ml++) {
            #pragma unroll
            for (int rh = 0; rh < 2; rh++) {
                int m = row0 + wm * 32 + ml * 16 + g + rh * 8;
                float* op = out + (size_t)m * LDW;
                #pragma unroll
                for (int nl = 0; nl < 8; nl++) {
                    int c = col0 + wn * 64 + nl * 8 + 2 * t;
                    float2 bv = *(const float2*)(bias + c);
                    float2 o;
                    o.x = acc[ml][nl][rh * 2 + 0] + bv.x;
                    o.y = acc[ml][nl][rh * 2 + 1] + bv.y;
                    *(float2*)(op + c) = o;
                }
            }
        }
    } else {
        #pragma unroll
        for (int ml = 0; ml < 2; ml++) {
            #pragma unroll
            for (int rh = 0; rh < 2; rh++) {
                int m = row0 + wm * 32 + ml * 16 + g + rh * 8;
                int b = m >> 11, n = m & 2047;
                int np = (n & ~7) | invperm8(n & 7);   // V row permutation
                #pragma unroll
                for (int nl = 0; nl < 8; nl++) {
                    #pragma unroll
                    for (int e = 0; e < 2; e++) {
                        int c = col0 + wn * 64 + nl * 8 + 2 * t + e;
                        float v = acc[ml][nl][rh * 2 + e] + __ldg(bias + c);
                        int sel = c % 3;
                        int hd  = c / 3;
                        int h   = hd / 96;
                        int d   = hd - h * 96;
                        float vr = __uint_as_float(tf32r(v));
                        size_t base = (size_t)(b * HH + h) * NN;
                        if (sel == 0)      g_Q[(base + n) * DD + perm8(d)] = vr;
                        else if (sel == 1) g_K[(base + n) * DD + perm8(d)] = vr;
                        else               g_V[(base + np) * DD + d]       = vr;
                    }
                }
            }
        }
    }
}

// ---------------------------------------------------------------------------
// Flash attention on mma.sync tf32, BN=128 keys/tile (16 tiles), 2-stage
// cp.async. BM=128 (8 warps x 16 rows -> warp-local softmax).
// g_Q/g_K permuted d -> uint2 frags. g_V rows pre-permuted in gmem so the
// S C-fragment registers feed the PV MMA A-operand DIRECTLY (no shuffles).
// ---------------------------------------------------------------------------
#define BNK 128
#define KVPAD 104
#define KVSZ (BNK * KVPAD)          // 13312 floats
#define ASTG (2 * KVSZ)
#define ASMEM (2 * ASTG * 4)        // 212992 B

__global__ __launch_bounds__(256) void attn_mma()
{
    extern __shared__ float sm[];

    const int tid  = threadIdx.x;
    const int lane = tid & 31;
    const int wid  = tid >> 5;
    const int g    = lane >> 2;
    const int t    = lane & 3;
    const int q0   = blockIdx.x * 128;
    const int bh   = blockIdx.y;
    const int b    = bh >> 3;
    const int h    = bh & 7;

    const float* Qg = g_Q + (size_t)bh * NN * DD;
    const float* Kg = g_K + (size_t)bh * NN * DD;
    const float* Vg = g_V + (size_t)bh * NN * DD;

    const int r0 = 16 * wid + g;
    const int r1 = r0 + 8;

    auto issueKV = [&](int kt, int s) {
        const int j0 = kt * BNK;
        float* bK = sm + s * ASTG;
        float* bV = bK + KVSZ;
        #pragma unroll
        for (int p = 0; p < 12; p++) {
            int i  = tid + p * 256;              // 3072 float4s per tensor
            int r  = i / 24, c4 = i % 24;
            cp16(bK + r * KVPAD + c4 * 4, Kg + (size_t)(j0 + r) * DD + c4 * 4);
            cp16(bV + r * KVPAD + c4 * 4, Vg + (size_t)(j0 + r) * DD + c4 * 4);
        }
        CP_COMMIT();
    };

    issueKV(0, 0);

    uint32_t qf[12][4];
    {
        const uint32_t* Q0 = (const uint32_t*)(Qg + (size_t)(q0 + r0) * DD);
        const uint32_t* Q1 = (const uint32_t*)(Qg + (size_t)(q0 + r1) * DD);
        #pragma unroll
        for (int c = 0; c < 12; c++) {
            uint2 v0 = *(const uint2*)&Q0[8 * c + 2 * t];
            uint2 v1 = *(const uint2*)&Q1[8 * c + 2 * t];
            qf[c][0] = v0.x; qf[c][2] = v0.y;
            qf[c][1] = v1.x; qf[c][3] = v1.y;
        }
    }

    float m0 = -1e30f, m1 = -1e30f, l0 = 0.f, l1 = 0.f;
    float oacc[12][4];
    #pragma unroll
    for (int dc = 0; dc < 12; dc++)
        #pragma unroll
        for (int e = 0; e < 4; e++) oacc[dc][e] = 0.f;

    #pragma unroll 1
    for (int kt = 0; kt < NN / BNK; kt++) {
        const int s = kt & 1;
        CP_WAIT0();
        __syncthreads();
        if (kt < NN / BNK - 1) issueKV(kt + 1, s ^ 1);

        const uint32_t* sKu = (const uint32_t*)(sm + s * ASTG);
        const uint32_t* sVu = sKu + KVSZ;

        // ---- S = Q K^T : 16 n-chunks x 12 k-chunks ----
        float sacc[16][4];
        #pragma unroll
        for (int nc = 0; nc < 16; nc++)
            #pragma unroll
            for (int e = 0; e < 4; e++) sacc[nc][e] = 0.f;

        #pragma unroll
        for (int kc = 0; kc < 12; kc++) {
            #pragma unroll
            for (int nc = 0; nc < 16; nc++) {
                uint2 v = *(const uint2*)&sKu[(nc * 8 + g) * KVPAD + kc * 8 + 2 * t];
                uint32_t bf[2] = { v.x, v.y };
                mma_tf32(sacc[nc], qf[kc], bf);
            }
        }

        // ---- online softmax (warp-local rows r0, r1) ----
        float lm0 = sacc[0][0], lm1 = sacc[0][2];
        #pragma unroll
        for (int nc = 0; nc < 16; nc++) {
            lm0 = fmaxf(lm0, fmaxf(sacc[nc][0], sacc[nc][1]));
            lm1 = fmaxf(lm1, fmaxf(sacc[nc][2], sacc[nc][3]));
        }
        lm0 = fmaxf(lm0, __shfl_xor_sync(0xffffffffu, lm0, 1));
        lm0 = fmaxf(lm0, __shfl_xor_sync(0xffffffffu, lm0, 2));
        lm1 = fmaxf(lm1, __shfl_xor_sync(0xffffffffu, lm1, 1));
        lm1 = fmaxf(lm1, __shfl_xor_sync(0xffffffffu, lm1, 2));

        const float mn0 = fmaxf(m0, lm0);
        const float mn1 = fmaxf(m1, lm1);
        const float sc0 = __expf(m0 - mn0);
        const float sc1 = __expf(m1 - mn1);
        m0 = mn0; m1 = mn1;

        float rs0 = 0.f, rs1 = 0.f;
        #pragma unroll
        for (int nc = 0; nc < 16; nc++) {
            sacc[nc][0] = __expf(sacc[nc][0] - mn0);
            sacc[nc][1] = __expf(sacc[nc][1] - mn0);
            sacc[nc][2] = __expf(sacc[nc][2] - mn1);
            sacc[nc][3] = __expf(sacc[nc][3] - mn1);
            rs0 += sacc[nc][0] + sacc[nc][1];
            rs1 += sacc[nc][2] + sacc[nc][3];
        }
        rs0 += __shfl_xor_sync(0xffffffffu, rs0, 1);
        rs0 += __shfl_xor_sync(0xffffffffu, rs0, 2);
        rs1 += __shfl_xor_sync(0xffffffffu, rs1, 1);
        rs1 += __shfl_xor_sync(0xffffffffu, rs1, 2);
        l0 = l0 * sc0 + rs0;
        l1 = l1 * sc1 + rs1;

        if (__any_sync(0xffffffffu, (sc0 != 1.f) || (sc1 != 1.f))) {
            #pragma unroll
            for (int dc = 0; dc < 12; dc++) {
                oacc[dc][0] *= sc0; oacc[dc][1] *= sc0;
                oacc[dc][2] *= sc1; oacc[dc][3] *= sc1;
            }
        }

        // ---- O += P @ V : C-frags feed A directly (V rows pre-permuted) ----
        #pragma unroll
        for (int kc = 0; kc < 16; kc++) {
            uint32_t af[4];
            af[0] = tf32r(sacc[kc][0]);
            af[1] = tf32r(sacc[kc][2]);
            af[2] = tf32r(sacc[kc][1]);
            af[3] = tf32r(sacc[kc][3]);
            #pragma unroll
            for (int dc = 0; dc < 12; dc++) {
                uint32_t bf[2];
                bf[0] = sVu[(kc * 8 + t)     * KVPAD + dc * 8 + g];
                bf[1] = sVu[(kc * 8 + t + 4) * KVPAD + dc * 8 + g];
                mma_tf32(oacc[dc], af, bf);
            }
        }
    }

    // ---- epilogue: ctx = tf32r((O / l) * SCALING), plain e layout ----
    const float inv0 = SCALING / l0;
    const float inv1 = SCALING / l1;
    float* dst0 = g_ctx + ((size_t)b * NN + (q0 + r0)) * EE + h * DD;
    float* dst1 = g_ctx + ((size_t)b * NN + (q0 + r1)) * EE + h * DD;
    #pragma unroll
    for (int dc = 0; dc < 12; dc++) {
        float2 o0, o1;
        o0.x = __uint_as_float(tf32r(oacc[dc][0] * inv0));
        o0.y = __uint_as_float(tf32r(oacc[dc][1] * inv0));
        o1.x = __uint_as_float(tf32r(oacc[dc][2] * inv1));
        o1.y = __uint_as_float(tf32r(oacc[dc][3] * inv1));
        *(float2*)(dst0 + dc * 8 + 2 * t) = o0;
        *(float2*)(dst1 + dc * 8 + 2 * t) = o1;
    }
}

// ---------------------------------------------------------------------------
extern "C" void kernel_launch(void* const* d_in, const int* in_sizes, int n_in,
                              void* d_out, int out_size)
{
    const float* x     = (const float*)d_in[0];
    const float* Wqkv  = (const float*)d_in[1];
    const float* bqkv  = (const float*)d_in[2];
    const float* Wproj = (const float*)d_in[3];
    const float* bproj = (const float*)d_in[4];
    float* out = (float*)d_out;

    cudaFuncSetAttribute(gemm_tc<1, 2304>,
                         cudaFuncAttributeMaxDynamicSharedMemorySize, GSMEM);
    cudaFuncSetAttribute(gemm_tc<0, 768>,
                         cudaFuncAttributeMaxDynamicSharedMemorySize, GSMEM);
    cudaFuncSetAttribute(attn_mma,
                         cudaFuncAttributeMaxDynamicSharedMemorySize, ASMEM);

    // one launch rounds everything (counts are float4 units)
    round_all<<<(NX4 + NW4 + NP4 + 255) / 256, 256>>>(
        (const float4*)x, (const float4*)Wqkv, (const float4*)Wproj);

    dim3 g1(2304 / 128, 8192 / 128);      // 18 x 64
    gemm_tc<1, 2304><<<g1, 256, GSMEM>>>(bqkv, nullptr);

    dim3 g2(NN / 128, BB * HH);           // 16 x 32
    attn_mma<<<g2, 256, ASMEM>>>();

    dim3 g3(768 / 128, 8192 / 128);       // 6 x 64
    gemm_tc<0, 768><<<g3, 256, GSMEM>>>(bproj, out);
}